// round 12
// baseline (speedup 1.0000x reference)
#include <cuda_runtime.h>

#define FULLMASK 0xffffffffu

// ---------------- persistent device scratch ----------------
// Accumulator component-major: [n][12 comps][32 ch] (10 used, 2 pad never touched)
__device__ __align__(16) float g_acc[20000 * 384];         // 30.7 MB
__device__ float g_ptab[95 * 95 * 32];                     // 1.15 MB, L2-hot
__device__ int   g_pidx[200000];
__device__ __align__(16) float4 g_geo[200000];             // (C, vx, vy, vz)

__device__ __forceinline__ void red_add_v2(float* a, float x, float y) {
    asm volatile("red.global.add.v2.f32 [%0], {%1,%2};"
                 :: "l"(a), "f"(x), "f"(y) : "memory");
}
__device__ __forceinline__ float2 ffma2(float2 a, float2 b, float2 c) {
    float2 d;
    asm("fma.rn.f32x2 %0, %1, %2, %3;"
        : "=l"(*(unsigned long long*)&d)
        : "l"(*(unsigned long long*)&a),
          "l"(*(unsigned long long*)&b),
          "l"(*(unsigned long long*)&c));
    return d;
}

// ---------------- fused precompute: zero + geo/pidx + ptab ----------------
__global__ __launch_bounds__(256) void pre_kernel(
    const int* __restrict__ src, const int* __restrict__ dst,
    const int* __restrict__ ntype,
    const float* __restrict__ bdist, const float* __restrict__ bvec,
    const float* __restrict__ emb, const float* __restrict__ We2,
    const float* __restrict__ be2,
    int N, int E, int ntypes)
{
    int stride = gridDim.x * blockDim.x;
    int g = blockIdx.x * blockDim.x + threadIdx.x;
    int n4 = N * 96;   // N*384 floats / 4
    float4* acc4 = reinterpret_cast<float4*>(g_acc);
    float4 z = make_float4(0.f, 0.f, 0.f, 0.f);
    for (int i = g; i < n4; i += stride)
        if ((i % 96) < 80) acc4[i] = z;    // only the 10 used comps
    for (int e = g; e < E; e += stride) {
        g_pidx[e] = ntype[src[e]] * ntypes + ntype[dst[e]];
        float dd = bdist[e];
        float c = 0.5f * (__cosf(0.62831853071795864769f * dd) + 1.f);
        c = (dd <= 5.0f) ? c : 0.f;
        float bx = bvec[(size_t)e * 3], by = bvec[(size_t)e * 3 + 1], bz = bvec[(size_t)e * 3 + 2];
        float inv = rsqrtf(bx * bx + by * by + bz * bz);
        g_geo[e] = make_float4(c, bx * inv, by * inv, bz * inv);
    }
    // pair table directly from emb & We2 (warp per pair)
    int nw = stride >> 5;
    int wid = g >> 5;
    int u = threadIdx.x & 31;
    int npairs = ntypes * ntypes;
    for (int p = wid; p < npairs; p += nw) {
        int ts = p / ntypes, td = p - ts * ntypes;
        const float* es = emb + ts * 32;
        const float* ed = emb + td * 32;
        float s = be2[u];
#pragma unroll 8
        for (int k = 0; k < 32; k++) {
            s = fmaf(__ldg(es + k), We2[k * 32 + u], s);
            s = fmaf(__ldg(ed + k), We2[(k + 32) * 32 + u], s);
        }
        g_ptab[(size_t)p * 32 + u] = s;
    }
}

// ---------------- edge phase: warp-pair cooperative ----------------
// 256 threads = 8 warps = 4 pairs. Pair shares one 16-edge a-tile.
// Warp role 0 computes (W1,W2) + REDs for comps 0..3; role 1 computes (W3,EF)
// + EF stores + REDs for comps 4..9. Lane l = (channel pair c=l&15, half h).
struct alignas(16) EdgeSmemP {
    float4 WaP[64 * 16];        // (w1[2c],w1[2c+1],w2[2c],w2[2c+1])[k][c] 16 KB
    float4 WbP[64 * 16];        // (w3[2c],w3[2c+1],we[2c],we[2c+1])      16 KB
    float4 adup[4][64][9];      // per-pair [k][q(8 used)+pad]            36.9 KB
    float4 geos[4][16];
    int    dns[4][16];
    int    pids[4][16];
};
static constexpr int EDGE_SMEM = (int)sizeof(EdgeSmemP);

__global__ __launch_bounds__(256, 3) void edge_kernel(
    const float* __restrict__ ea, const int* __restrict__ dst,
    const float* __restrict__ Wd1, const float* __restrict__ bd1,
    const float* __restrict__ Wd2, const float* __restrict__ bd2,
    const float* __restrict__ Wd3, const float* __restrict__ bd3,
    const float* __restrict__ We3, const float* __restrict__ be3,
    float* __restrict__ outEF, int E)
{
    extern __shared__ __align__(16) char smraw[];
    EdgeSmemP& sm = *reinterpret_cast<EdgeSmemP*>(smraw);
    int tid = threadIdx.x;
    for (int i = tid; i < 64 * 16; i += 256) {
        int k = i >> 4, c2 = (i & 15) * 2;
        sm.WaP[i] = make_float4(Wd1[k * 32 + c2], Wd1[k * 32 + c2 + 1],
                                Wd2[k * 32 + c2], Wd2[k * 32 + c2 + 1]);
        sm.WbP[i] = make_float4(Wd3[k * 32 + c2], Wd3[k * 32 + c2 + 1],
                                We3[k * 32 + c2], We3[k * 32 + c2 + 1]);
    }
    __syncthreads();
    const int u = tid & 31, w = tid >> 5;
    const int p = w >> 1, role = w & 1;
    const int c = u & 15, h = u >> 4;
    const int bar_id = 1 + p;
    // role 0: m0=W1 (bias bd1), m1=W2 (bias bd2); role 1: m0=W3 (bd3), m1=EF (be3)
    const float* bp0 = role ? bd3 : bd1;
    const float* bp1 = role ? be3 : bd2;
    const float2 bias0 = make_float2(bp0[2 * c], bp0[2 * c + 1]);
    const float2 bias1 = make_float2(bp1[2 * c], bp1[2 * c + 1]);
    const float4* Wrole = role ? sm.WbP : sm.WaP;
    int gp = blockIdx.x * 4 + p;
    int np = gridDim.x * 4;
    int ngroups = (E + 15) >> 4;
    for (int g = gp; g < ngroups; g += np) {
        int e0 = g * 16;
        asm volatile("bar.sync %0, 64;" :: "r"(bar_id) : "memory");
        // ---- cooperative stage: role 0 -> k rows 0..31, role 1 -> 32..63 ----
        {
            float av[16];
#pragma unroll
            for (int j = 0; j < 16; j++) {
                int e = min(e0 + j, E - 1);
                av[j] = ea[(size_t)e * 64 + role * 32 + u];
            }
#pragma unroll
            for (int q = 0; q < 8; q++)
                sm.adup[p][u + role * 32][q] =
                    make_float4(av[2 * q], av[2 * q], av[2 * q + 1], av[2 * q + 1]);
            if (role == 0 && u < 16) {
                int e = min(e0 + u, E - 1);
                sm.geos[p][u] = g_geo[e];
                sm.dns[p][u] = dst[e];
                sm.pids[p][u] = g_pidx[e];
            }
        }
        asm volatile("bar.sync %0, 64;" :: "r"(bar_id) : "memory");
        // ---- GEMV mainloop: 2 mats x 16 edges (8 per lane-half) ----
        float2 m0[8], m1[8];
#pragma unroll
        for (int j = 0; j < 8; j++) { m0[j] = bias0; m1[j] = bias1; }
#pragma unroll 2
        for (int k = 0; k < 64; k++) {
            float4 wa = Wrole[k * 16 + c];
            float4 A0 = sm.adup[p][k][4 * h + 0];
            float4 A1 = sm.adup[p][k][4 * h + 1];
            float4 A2 = sm.adup[p][k][4 * h + 2];
            float4 A3 = sm.adup[p][k][4 * h + 3];
            float2 d0 = make_float2(wa.x, wa.y);
            float2 d1 = make_float2(wa.z, wa.w);
            float2 ap0 = make_float2(A0.x, A0.y), ap1 = make_float2(A0.z, A0.w);
            float2 ap2 = make_float2(A1.x, A1.y), ap3 = make_float2(A1.z, A1.w);
            float2 ap4 = make_float2(A2.x, A2.y), ap5 = make_float2(A2.z, A2.w);
            float2 ap6 = make_float2(A3.x, A3.y), ap7 = make_float2(A3.z, A3.w);
            m0[0] = ffma2(ap0, d0, m0[0]); m1[0] = ffma2(ap0, d1, m1[0]);
            m0[1] = ffma2(ap1, d0, m0[1]); m1[1] = ffma2(ap1, d1, m1[1]);
            m0[2] = ffma2(ap2, d0, m0[2]); m1[2] = ffma2(ap2, d1, m1[2]);
            m0[3] = ffma2(ap3, d0, m0[3]); m1[3] = ffma2(ap3, d1, m1[3]);
            m0[4] = ffma2(ap4, d0, m0[4]); m1[4] = ffma2(ap4, d1, m1[4]);
            m0[5] = ffma2(ap5, d0, m0[5]); m1[5] = ffma2(ap5, d1, m1[5]);
            m0[6] = ffma2(ap6, d0, m0[6]); m1[6] = ffma2(ap6, d1, m1[6]);
            m0[7] = ffma2(ap7, d0, m0[7]); m1[7] = ffma2(ap7, d1, m1[7]);
        }
        // ---- epilogue (no shared a-tile access; next overwrite gated by bar) ----
        if (role) {
            // EF stores first
#pragma unroll
            for (int j = 0; j < 8; j++) {
                int e = e0 + 8 * h + j;
                if (e < E) *reinterpret_cast<float2*>(&outEF[(size_t)e * 32 + 2 * c]) = m1[j];
            }
        }
        float2 zjv[8];
#pragma unroll
        for (int j = 0; j < 8; j++)
            zjv[j] = *reinterpret_cast<const float2*>(
                &g_ptab[(size_t)sm.pids[p][8 * h + j] * 32 + 2 * c]);
#pragma unroll
        for (int j = 0; j < 8; j++) {
            int el = 8 * h + j;
            int e = e0 + el;
            if (e >= E) continue;
            float4 gg = sm.geos[p][el];
            int dnj = sm.dns[p][el];
            float C = gg.x, vx = gg.y, vy = gg.z, vz = gg.w;
            float zcx = zjv[j].x * C, zcy = zjv[j].y * C;
            float* base = g_acc + (size_t)dnj * 384 + 2 * c;
            if (role) {
                float qx = zcx * m0[j].x, qy = zcy * m0[j].y;
                red_add_v2(base + 128, qx * vx * vx, qy * vx * vx);
                red_add_v2(base + 160, qx * vy * vy, qy * vy * vy);
                red_add_v2(base + 192, qx * vz * vz, qy * vz * vz);
                red_add_v2(base + 224, qx * vx * vy, qy * vx * vy);
                red_add_v2(base + 256, qx * vx * vz, qy * vx * vz);
                red_add_v2(base + 288, qx * vy * vz, qy * vy * vz);
            } else {
                float fIx = zcx * m0[j].x, fIy = zcy * m0[j].y;
                float px = zcx * m1[j].x, py = zcy * m1[j].y;
                red_add_v2(base,       fIx,     fIy);
                red_add_v2(base + 32,  px * vx, py * vx);
                red_add_v2(base + 64,  px * vy, py * vy);
                red_add_v2(base + 96,  px * vz, py * vz);
            }
        }
    }
}

// ---------------- node epilogue ----------------
__global__ __launch_bounds__(256) void node_kernel(
    const float* __restrict__ Ws1, const float* __restrict__ bs1,
    const float* __restrict__ Ws2, const float* __restrict__ bs2,
    const float* __restrict__ Wt0, const float* __restrict__ Wt1, const float* __restrict__ Wt2,
    const float* __restrict__ lng, const float* __restrict__ lnb,
    float* __restrict__ outX, int N)
{
    __shared__ float Ws1s[32 * 64];
    __shared__ float Ws2s[64 * 96];
    __shared__ float Wt0s[32 * 32], Wt1s[32 * 32], Wt2s[32 * 32];
    __shared__ float bs1s[64], bs2s[96], lngs[32], lnbs[32];
    __shared__ float wbuf[8][64];
    int tid = threadIdx.x;
    for (int i = tid; i < 32 * 64; i += 256) Ws1s[i] = Ws1[i];
    for (int i = tid; i < 64 * 96; i += 256) Ws2s[i] = Ws2[i];
    for (int i = tid; i < 32 * 32; i += 256) { Wt0s[i] = Wt0[i]; Wt1s[i] = Wt1[i]; Wt2s[i] = Wt2[i]; }
    if (tid < 64) bs1s[tid] = bs1[tid];
    if (tid < 96) bs2s[tid] = bs2[tid];
    if (tid < 32) { lngs[tid] = lng[tid]; lnbs[tid] = lnb[tid]; }
    __syncthreads();
    const int u = tid & 31, w = tid >> 5;
    float* wb = wbuf[w];
    int gw = blockIdx.x * 8 + w, nw = gridDim.x * 8;
    for (int n = gw; n < N; n += nw) {
        const float* base = g_acc + (size_t)n * 384 + u;
        float sI  = base[0];
        float wx  = base[32],  float_wy = base[64];
        float wy = float_wy, wz = base[96];
        float Mxx = base[128], Myy = base[160], Mzz = base[192];
        float Mxy = base[224], Mxz = base[256], Myz = base[288];
        float trM = Mxx + Myy + Mzz;
        float dg = sI - trM * (1.f / 3.f);
        float t00 = dg + Mxx, t11 = dg + Myy, t22 = dg + Mzz;
        float nr = t00 * t00 + t11 * t11 + t22 * t22
                 + 2.f * (Mxy * Mxy + wz * wz + Mxz * Mxz + wy * wy + Myz * Myz + wx * wx);
        float s = nr;
#pragma unroll
        for (int o = 16; o; o >>= 1) s += __shfl_xor_sync(FULLMASK, s, o);
        float mu = s * (1.f / 32.f);
        float dv = nr - mu;
        float v2 = dv * dv;
#pragma unroll
        for (int o = 16; o; o >>= 1) v2 += __shfl_xor_sync(FULLMASK, v2, o);
        float y = dv * rsqrtf(v2 * (1.f / 32.f) + 1e-5f) * lngs[u] + lnbs[u];
        wb[u] = y;
        __syncwarp();
        float h1a = bs1s[u], h1b = bs1s[u + 32];
#pragma unroll 8
        for (int k = 0; k < 32; k++) {
            float t = wb[k];
            h1a = fmaf(t, Ws1s[k * 64 + u], h1a);
            h1b = fmaf(t, Ws1s[k * 64 + u + 32], h1b);
        }
        h1a = h1a / (1.f + __expf(-h1a));
        h1b = h1b / (1.f + __expf(-h1b));
        __syncwarp();
        wb[u] = h1a; wb[u + 32] = h1b;
        __syncwarp();
        float s0 = bs2s[3 * u], s1 = bs2s[3 * u + 1], s2 = bs2s[3 * u + 2];
#pragma unroll 8
        for (int k = 0; k < 64; k++) {
            float t = wb[k];
            s0 = fmaf(t, Ws2s[k * 96 + 3 * u], s0);
            s1 = fmaf(t, Ws2s[k * 96 + 3 * u + 1], s1);
            s2 = fmaf(t, Ws2s[k * 96 + 3 * u + 2], s2);
        }
        s0 = s0 / (1.f + __expf(-s0));
        s1 = s1 / (1.f + __expf(-s1));
        s2 = s2 / (1.f + __expf(-s2));
        float pI = 0, px = 0, py = 0, pz = 0, pxx = 0, pyy = 0, pzz = 0, pxy = 0, pxz = 0, pyz = 0;
#pragma unroll 4
        for (int k = 0; k < 32; k++) {
            float w0v = Wt0s[k * 32 + u], w1v = Wt1s[k * 32 + u], w2v = Wt2s[k * 32 + u];
            pI  = fmaf(__shfl_sync(FULLMASK, sI,  k), w0v, pI);
            px  = fmaf(__shfl_sync(FULLMASK, wx,  k), w1v, px);
            py  = fmaf(__shfl_sync(FULLMASK, wy,  k), w1v, py);
            pz  = fmaf(__shfl_sync(FULLMASK, wz,  k), w1v, pz);
            pxx = fmaf(__shfl_sync(FULLMASK, Mxx, k), w2v, pxx);
            pyy = fmaf(__shfl_sync(FULLMASK, Myy, k), w2v, pyy);
            pzz = fmaf(__shfl_sync(FULLMASK, Mzz, k), w2v, pzz);
            pxy = fmaf(__shfl_sync(FULLMASK, Mxy, k), w2v, pxy);
            pxz = fmaf(__shfl_sync(FULLMASK, Mxz, k), w2v, pxz);
            pyz = fmaf(__shfl_sync(FULLMASK, Myz, k), w2v, pyz);
        }
        float t3 = (pxx + pyy + pzz) * (1.f / 3.f);
        float* o = outX + ((size_t)n * 32 + u) * 9;
        o[0] =  s0 * pI + s2 * (pxx - t3);
        o[1] = -s1 * pz + s2 * pxy;
        o[2] =  s1 * py + s2 * pxz;
        o[3] =  s1 * pz + s2 * pxy;
        o[4] =  s0 * pI + s2 * (pyy - t3);
        o[5] = -s1 * px + s2 * pyz;
        o[6] = -s1 * py + s2 * pxz;
        o[7] =  s1 * px + s2 * pyz;
        o[8] =  s0 * pI + s2 * (pzz - t3);
        __syncwarp();
    }
}

extern "C" void kernel_launch(void* const* d_in, const int* in_sizes, int n_in,
                              void* d_out, int out_size) {
    (void)n_in; (void)out_size;
    const int*   node_type = (const int*)d_in[0];
    const float* edge_attr = (const float*)d_in[1];
    const float* bond_dist = (const float*)d_in[2];
    const float* bond_vec  = (const float*)d_in[3];
    const int*   src = (const int*)d_in[4];
    const int*   dst = (const int*)d_in[5];
    const float* emb = (const float*)d_in[6];
    const float* Wd1 = (const float*)d_in[7];  const float* bd1 = (const float*)d_in[8];
    const float* Wd2 = (const float*)d_in[9];  const float* bd2 = (const float*)d_in[10];
    const float* Wd3 = (const float*)d_in[11]; const float* bd3 = (const float*)d_in[12];
    const float* We2 = (const float*)d_in[13]; const float* be2 = (const float*)d_in[14];
    const float* We3 = (const float*)d_in[15]; const float* be3 = (const float*)d_in[16];
    const float* Wt0 = (const float*)d_in[17];
    const float* Wt1 = (const float*)d_in[18];
    const float* Wt2 = (const float*)d_in[19];
    const float* Ws1 = (const float*)d_in[20]; const float* bs1 = (const float*)d_in[21];
    const float* Ws2 = (const float*)d_in[22]; const float* bs2 = (const float*)d_in[23];
    const float* lng = (const float*)d_in[24]; const float* lnb = (const float*)d_in[25];

    int N = in_sizes[0];
    int E = in_sizes[2];
    int ntypes = in_sizes[6] / 32;
    float* outX  = (float*)d_out;
    float* outEF = outX + (size_t)N * 32 * 9;

    cudaFuncSetAttribute(edge_kernel, cudaFuncAttributeMaxDynamicSharedMemorySize, EDGE_SMEM);

    pre_kernel<<<1024, 256>>>(src, dst, node_type, bond_dist, bond_vec,
                              emb, We2, be2, N, E, ntypes);
    edge_kernel<<<444, 256, EDGE_SMEM>>>(edge_attr, dst, Wd1, bd1, Wd2, bd2, Wd3, bd3,
                                         We3, be3, outEF, E);
    node_kernel<<<592, 256>>>(Ws1, bs1, Ws2, bs2, Wt0, Wt1, Wt2, lng, lnb, outX, N);
}

// round 13
// speedup vs baseline: 1.1316x; 1.1316x over previous
#include <cuda_runtime.h>

#define FULLMASK 0xffffffffu

// ---------------- persistent device scratch ----------------
// Accumulator component-major: [n][12 comps][32 ch] (10 used, 2 pad never touched)
__device__ __align__(16) float g_acc[20000 * 384];         // 30.7 MB
__device__ float g_ZhS[95 * 32];
__device__ float g_ZhD[95 * 32];
__device__ float g_ptab[95 * 95 * 32];                     // 1.15 MB, L2-hot
__device__ int   g_pidx[200000];
__device__ __align__(16) float4 g_geo[200000];             // (C, vx, vy, vz)

__device__ __forceinline__ void red_add_v2(float* a, float x, float y) {
    asm volatile("red.global.add.v2.f32 [%0], {%1,%2};"
                 :: "l"(a), "f"(x), "f"(y) : "memory");
}
__device__ __forceinline__ float2 ffma2(float2 a, float2 b, float2 c) {
    float2 d;
    asm("fma.rn.f32x2 %0, %1, %2, %3;"
        : "=l"(*(unsigned long long*)&d)
        : "l"(*(unsigned long long*)&a),
          "l"(*(unsigned long long*)&b),
          "l"(*(unsigned long long*)&c));
    return d;
}

// ---------------- tiny precompute kernels (R9 exact) ----------------
__global__ void zh_kernel(const float* __restrict__ emb, const float* __restrict__ We2,
                          int ntypes) {
    int t = blockIdx.x;
    if (t >= ntypes) return;
    int u = threadIdx.x & 31;
    int half = threadIdx.x >> 5;
    float s = 0.f;
#pragma unroll 8
    for (int k = 0; k < 32; k++)
        s = fmaf(emb[t * 32 + k], We2[(k + half * 32) * 32 + u], s);
    (half ? g_ZhD : g_ZhS)[t * 32 + u] = s;
}

__global__ __launch_bounds__(256) void ptab_kernel(const float* __restrict__ be2, int ntypes) {
    int w = blockIdx.x * 8 + (threadIdx.x >> 5);
    int npairs = ntypes * ntypes;
    if (w >= npairs) return;
    int u = threadIdx.x & 31;
    int ts = w / ntypes, td = w - ts * ntypes;
    g_ptab[w * 32 + u] = g_ZhS[ts * 32 + u] + g_ZhD[td * 32 + u] + be2[u];
}

__global__ void prep_kernel(const int* __restrict__ src, const int* __restrict__ dst,
                            const int* __restrict__ ntype,
                            const float* __restrict__ bdist, const float* __restrict__ bvec,
                            int N, int E, int ntypes) {
    int stride = gridDim.x * blockDim.x;
    int g = blockIdx.x * blockDim.x + threadIdx.x;
    int n4 = N * 96;   // N*384 floats / 4
    float4* acc4 = reinterpret_cast<float4*>(g_acc);
    float4 z = make_float4(0.f, 0.f, 0.f, 0.f);
    for (int i = g; i < n4; i += stride)
        if ((i % 96) < 80) acc4[i] = z;    // only the 10 used comps
    for (int e = g; e < E; e += stride) {
        g_pidx[e] = ntype[src[e]] * ntypes + ntype[dst[e]];
        float dd = bdist[e];
        float c = 0.5f * (__cosf(0.62831853071795864769f * dd) + 1.f);
        c = (dd <= 5.0f) ? c : 0.f;
        float bx = bvec[(size_t)e * 3], by = bvec[(size_t)e * 3 + 1], bz = bvec[(size_t)e * 3 + 2];
        float inv = rsqrtf(bx * bx + by * by + bz * bz);
        g_geo[e] = make_float4(c, bx * inv, by * inv, bz * inv);
    }
}

// ---------------- edge phase (R9 exact: 16 edges/warp, unroll 2) ----------------
struct alignas(16) EdgeSmem16 {
    float4 WaP[64 * 16];
    float4 WbP[64 * 16];
    float4 adup[8][64][9];
    float4 geos[8][16];
    int    dns[8][16];
    int    pids[8][16];
};
static constexpr int EDGE_SMEM = (int)sizeof(EdgeSmem16);

__global__ __launch_bounds__(256, 2) void edge_kernel(
    const float* __restrict__ ea, const int* __restrict__ dst,
    const float* __restrict__ Wd1, const float* __restrict__ bd1,
    const float* __restrict__ Wd2, const float* __restrict__ bd2,
    const float* __restrict__ Wd3, const float* __restrict__ bd3,
    const float* __restrict__ We3, const float* __restrict__ be3,
    float* __restrict__ outEF, int E)
{
    extern __shared__ __align__(16) char smraw[];
    EdgeSmem16& sm = *reinterpret_cast<EdgeSmem16*>(smraw);
    int tid = threadIdx.x;
    for (int i = tid; i < 64 * 16; i += 256) {
        int k = i >> 4, c2 = (i & 15) * 2;
        sm.WaP[i] = make_float4(Wd1[k * 32 + c2], Wd1[k * 32 + c2 + 1],
                                Wd2[k * 32 + c2], Wd2[k * 32 + c2 + 1]);
        sm.WbP[i] = make_float4(Wd3[k * 32 + c2], Wd3[k * 32 + c2 + 1],
                                We3[k * 32 + c2], We3[k * 32 + c2 + 1]);
    }
    __syncthreads();
    const int u = tid & 31, w = tid >> 5;
    const int c = u & 15, h = u >> 4;
    const float2 bias1 = make_float2(bd1[2 * c], bd1[2 * c + 1]);
    const float2 bias2 = make_float2(bd2[2 * c], bd2[2 * c + 1]);
    const float2 bias3 = make_float2(bd3[2 * c], bd3[2 * c + 1]);
    const float2 biase = make_float2(be3[2 * c], be3[2 * c + 1]);
    int gw = blockIdx.x * 8 + w;
    int nw = gridDim.x * 8;
    int ngroups = (E + 15) >> 4;
    for (int g = gw; g < ngroups; g += nw) {
        int e0 = g * 16;
        __syncwarp();
        {
            float a0[16], a1[16];
#pragma unroll
            for (int j = 0; j < 16; j++) {
                int e = min(e0 + j, E - 1);
                a0[j] = ea[(size_t)e * 64 + u];
                a1[j] = ea[(size_t)e * 64 + 32 + u];
            }
#pragma unroll
            for (int q = 0; q < 8; q++) {
                sm.adup[w][u][q]      = make_float4(a0[2 * q], a0[2 * q], a0[2 * q + 1], a0[2 * q + 1]);
                sm.adup[w][u + 32][q] = make_float4(a1[2 * q], a1[2 * q], a1[2 * q + 1], a1[2 * q + 1]);
            }
            if (u < 16) {
                int e = min(e0 + u, E - 1);
                sm.geos[w][u] = g_geo[e];
                sm.dns[w][u] = dst[e];
                sm.pids[w][u] = g_pidx[e];
            }
        }
        __syncwarp();
        float2 w1[8], w2[8], w3[8], ef[8];
#pragma unroll
        for (int j = 0; j < 8; j++) { w1[j] = bias1; w2[j] = bias2; w3[j] = bias3; ef[j] = biase; }
#pragma unroll 2
        for (int k = 0; k < 64; k++) {
            float4 wa = sm.WaP[k * 16 + c];
            float4 wb = sm.WbP[k * 16 + c];
            float4 A0 = sm.adup[w][k][4 * h + 0];
            float4 A1 = sm.adup[w][k][4 * h + 1];
            float4 A2 = sm.adup[w][k][4 * h + 2];
            float4 A3 = sm.adup[w][k][4 * h + 3];
            float2 d1 = make_float2(wa.x, wa.y);
            float2 d2 = make_float2(wa.z, wa.w);
            float2 d3 = make_float2(wb.x, wb.y);
            float2 de = make_float2(wb.z, wb.w);
            float2 ap0 = make_float2(A0.x, A0.y), ap1 = make_float2(A0.z, A0.w);
            float2 ap2 = make_float2(A1.x, A1.y), ap3 = make_float2(A1.z, A1.w);
            float2 ap4 = make_float2(A2.x, A2.y), ap5 = make_float2(A2.z, A2.w);
            float2 ap6 = make_float2(A3.x, A3.y), ap7 = make_float2(A3.z, A3.w);
            w1[0] = ffma2(ap0, d1, w1[0]); w2[0] = ffma2(ap0, d2, w2[0]);
            w3[0] = ffma2(ap0, d3, w3[0]); ef[0] = ffma2(ap0, de, ef[0]);
            w1[1] = ffma2(ap1, d1, w1[1]); w2[1] = ffma2(ap1, d2, w2[1]);
            w3[1] = ffma2(ap1, d3, w3[1]); ef[1] = ffma2(ap1, de, ef[1]);
            w1[2] = ffma2(ap2, d1, w1[2]); w2[2] = ffma2(ap2, d2, w2[2]);
            w3[2] = ffma2(ap2, d3, w3[2]); ef[2] = ffma2(ap2, de, ef[2]);
            w1[3] = ffma2(ap3, d1, w1[3]); w2[3] = ffma2(ap3, d2, w2[3]);
            w3[3] = ffma2(ap3, d3, w3[3]); ef[3] = ffma2(ap3, de, ef[3]);
            w1[4] = ffma2(ap4, d1, w1[4]); w2[4] = ffma2(ap4, d2, w2[4]);
            w3[4] = ffma2(ap4, d3, w3[4]); ef[4] = ffma2(ap4, de, ef[4]);
            w1[5] = ffma2(ap5, d1, w1[5]); w2[5] = ffma2(ap5, d2, w2[5]);
            w3[5] = ffma2(ap5, d3, w3[5]); ef[5] = ffma2(ap5, de, ef[5]);
            w1[6] = ffma2(ap6, d1, w1[6]); w2[6] = ffma2(ap6, d2, w2[6]);
            w3[6] = ffma2(ap6, d3, w3[6]); ef[6] = ffma2(ap6, de, ef[6]);
            w1[7] = ffma2(ap7, d1, w1[7]); w2[7] = ffma2(ap7, d2, w2[7]);
            w3[7] = ffma2(ap7, d3, w3[7]); ef[7] = ffma2(ap7, de, ef[7]);
        }
#pragma unroll
        for (int j = 0; j < 8; j++) {
            int el = 8 * h + j;
            int e = e0 + el;
            if (e < E) {
                *reinterpret_cast<float2*>(&outEF[(size_t)e * 32 + 2 * c]) = ef[j];
                float4 gg = sm.geos[w][el];
                int dnj = sm.dns[w][el];
                float2 zj = *reinterpret_cast<const float2*>(&g_ptab[(size_t)sm.pids[w][el] * 32 + 2 * c]);
                float C = gg.x, vx = gg.y, vy = gg.z, vz = gg.w;
                float zcx = zj.x * C, zcy = zj.y * C;
                float fIx = zcx * w1[j].x, fIy = zcy * w1[j].y;
                float px = zcx * w2[j].x, py = zcy * w2[j].y;
                float qx = zcx * w3[j].x, qy = zcy * w3[j].y;
                float* base = g_acc + (size_t)dnj * 384 + 2 * c;
                red_add_v2(base,       fIx,          fIy);
                red_add_v2(base + 32,  px * vx,      py * vx);
                red_add_v2(base + 64,  px * vy,      py * vy);
                red_add_v2(base + 96,  px * vz,      py * vz);
                red_add_v2(base + 128, qx * vx * vx, qy * vx * vx);
                red_add_v2(base + 160, qx * vy * vy, qy * vy * vy);
                red_add_v2(base + 192, qx * vz * vz, qy * vz * vz);
                red_add_v2(base + 224, qx * vx * vy, qy * vx * vy);
                red_add_v2(base + 256, qx * vx * vz, qy * vx * vz);
                red_add_v2(base + 288, qx * vy * vz, qy * vy * vz);
            }
        }
    }
}

// ---------------- node epilogue v2: smem-staged mixing, no shfl chains ----------------
struct alignas(16) NodeSmem {
    float  Ws1s[32 * 64];       //  8 KB
    float  Ws2s[64 * 96];       // 24 KB
    float  Wt0s[32 * 32];       //  4 KB
    float  Wt1s[32 * 32];       //  4 KB
    float  Wt2s[32 * 32];       //  4 KB
    float  bs1s[64], bs2s[96], lngs[32], lnbs[32];
    float  wbuf[8][64];         //  2 KB
    float4 comps[8][32][3];     // 12 KB : (sI,wx,wy,wz)(Mxx,Myy,Mzz,Mxy)(Mxz,Myz,-,-)
};
static constexpr int NODE_SMEM = (int)sizeof(NodeSmem);

__global__ __launch_bounds__(256, 3) void node_kernel(
    const float* __restrict__ Ws1, const float* __restrict__ bs1,
    const float* __restrict__ Ws2, const float* __restrict__ bs2,
    const float* __restrict__ Wt0, const float* __restrict__ Wt1, const float* __restrict__ Wt2,
    const float* __restrict__ lng, const float* __restrict__ lnb,
    float* __restrict__ outX, int N)
{
    extern __shared__ __align__(16) char smraw[];
    NodeSmem& sm = *reinterpret_cast<NodeSmem*>(smraw);
    int tid = threadIdx.x;
    for (int i = tid; i < 32 * 64; i += 256) sm.Ws1s[i] = Ws1[i];
    for (int i = tid; i < 64 * 96; i += 256) sm.Ws2s[i] = Ws2[i];
    for (int i = tid; i < 32 * 32; i += 256) {
        sm.Wt0s[i] = Wt0[i]; sm.Wt1s[i] = Wt1[i]; sm.Wt2s[i] = Wt2[i];
    }
    if (tid < 64) sm.bs1s[tid] = bs1[tid];
    if (tid < 96) sm.bs2s[tid] = bs2[tid];
    if (tid < 32) { sm.lngs[tid] = lng[tid]; sm.lnbs[tid] = lnb[tid]; }
    __syncthreads();
    const int u = tid & 31, w = tid >> 5;
    float* wb = sm.wbuf[w];
    int gw = blockIdx.x * 8 + w, nw = gridDim.x * 8;
    for (int n = gw; n < N; n += nw) {
        const float* base = g_acc + (size_t)n * 384 + u;
        float sI  = base[0];
        float wx  = base[32],  wy  = base[64],  wz  = base[96];
        float Mxx = base[128], Myy = base[160], Mzz = base[192];
        float Mxy = base[224], Mxz = base[256], Myz = base[288];
        // stage components for the mixing loop (read via broadcast LDS later)
        sm.comps[w][u][0] = make_float4(sI, wx, wy, wz);
        sm.comps[w][u][1] = make_float4(Mxx, Myy, Mzz, Mxy);
        sm.comps[w][u][2] = make_float4(Mxz, Myz, 0.f, 0.f);
        float trM = Mxx + Myy + Mzz;
        float dg = sI - trM * (1.f / 3.f);
        float t00 = dg + Mxx, t11 = dg + Myy, t22 = dg + Mzz;
        float nr = t00 * t00 + t11 * t11 + t22 * t22
                 + 2.f * (Mxy * Mxy + wz * wz + Mxz * Mxz + wy * wy + Myz * Myz + wx * wx);
        float s = nr;
#pragma unroll
        for (int o = 16; o; o >>= 1) s += __shfl_xor_sync(FULLMASK, s, o);
        float mu = s * (1.f / 32.f);
        float dv = nr - mu;
        float v2 = dv * dv;
#pragma unroll
        for (int o = 16; o; o >>= 1) v2 += __shfl_xor_sync(FULLMASK, v2, o);
        float y = dv * rsqrtf(v2 * (1.f / 32.f) + 1e-5f) * sm.lngs[u] + sm.lnbs[u];
        wb[u] = y;
        __syncwarp();
        float h1a = sm.bs1s[u], h1b = sm.bs1s[u + 32];
#pragma unroll 8
        for (int k = 0; k < 32; k++) {
            float t = wb[k];
            h1a = fmaf(t, sm.Ws1s[k * 64 + u], h1a);
            h1b = fmaf(t, sm.Ws1s[k * 64 + u + 32], h1b);
        }
        h1a = h1a / (1.f + __expf(-h1a));
        h1b = h1b / (1.f + __expf(-h1b));
        __syncwarp();
        wb[u] = h1a; wb[u + 32] = h1b;
        __syncwarp();
        float s0 = sm.bs2s[3 * u], s1 = sm.bs2s[3 * u + 1], s2 = sm.bs2s[3 * u + 2];
#pragma unroll 8
        for (int k = 0; k < 64; k++) {
            float t = wb[k];
            s0 = fmaf(t, sm.Ws2s[k * 96 + 3 * u], s0);
            s1 = fmaf(t, sm.Ws2s[k * 96 + 3 * u + 1], s1);
            s2 = fmaf(t, sm.Ws2s[k * 96 + 3 * u + 2], s2);
        }
        s0 = s0 / (1.f + __expf(-s0));
        s1 = s1 / (1.f + __expf(-s1));
        s2 = s2 / (1.f + __expf(-s2));
        // ---- mixing: 5 packed accumulators, broadcast LDS operands ----
        float2 A0 = make_float2(0.f, 0.f);   // (pI,  px)
        float2 A1 = make_float2(0.f, 0.f);   // (py,  pz)
        float2 A2 = make_float2(0.f, 0.f);   // (pxx, pyy)
        float2 A3 = make_float2(0.f, 0.f);   // (pzz, pxy)
        float2 A4 = make_float2(0.f, 0.f);   // (pxz, pyz)
#pragma unroll 4
        for (int k = 0; k < 32; k++) {
            float w0v = sm.Wt0s[k * 32 + u];
            float w1v = sm.Wt1s[k * 32 + u];
            float w2v = sm.Wt2s[k * 32 + u];
            float4 c01 = sm.comps[w][k][0];
            float4 c2  = sm.comps[w][k][1];
            float4 c3  = sm.comps[w][k][2];
            A0 = ffma2(make_float2(c01.x, c01.y), make_float2(w0v, w1v), A0);
            A1 = ffma2(make_float2(c01.z, c01.w), make_float2(w1v, w1v), A1);
            A2 = ffma2(make_float2(c2.x,  c2.y ), make_float2(w2v, w2v), A2);
            A3 = ffma2(make_float2(c2.z,  c2.w ), make_float2(w2v, w2v), A3);
            A4 = ffma2(make_float2(c3.x,  c3.y ), make_float2(w2v, w2v), A4);
        }
        float pI = A0.x, px = A0.y, py = A1.x, pz = A1.y;
        float pxx = A2.x, pyy = A2.y, pzz = A3.x, pxy = A3.y, pxz = A4.x, pyz = A4.y;
        float t3 = (pxx + pyy + pzz) * (1.f / 3.f);
        float* o = outX + ((size_t)n * 32 + u) * 9;
        o[0] =  s0 * pI + s2 * (pxx - t3);
        o[1] = -s1 * pz + s2 * pxy;
        o[2] =  s1 * py + s2 * pxz;
        o[3] =  s1 * pz + s2 * pxy;
        o[4] =  s0 * pI + s2 * (pyy - t3);
        o[5] = -s1 * px + s2 * pyz;
        o[6] = -s1 * py + s2 * pxz;
        o[7] =  s1 * px + s2 * pyz;
        o[8] =  s0 * pI + s2 * (pzz - t3);
        __syncwarp();
    }
}

extern "C" void kernel_launch(void* const* d_in, const int* in_sizes, int n_in,
                              void* d_out, int out_size) {
    (void)n_in; (void)out_size;
    const int*   node_type = (const int*)d_in[0];
    const float* edge_attr = (const float*)d_in[1];
    const float* bond_dist = (const float*)d_in[2];
    const float* bond_vec  = (const float*)d_in[3];
    const int*   src = (const int*)d_in[4];
    const int*   dst = (const int*)d_in[5];
    const float* emb = (const float*)d_in[6];
    const float* Wd1 = (const float*)d_in[7];  const float* bd1 = (const float*)d_in[8];
    const float* Wd2 = (const float*)d_in[9];  const float* bd2 = (const float*)d_in[10];
    const float* Wd3 = (const float*)d_in[11]; const float* bd3 = (const float*)d_in[12];
    const float* We2 = (const float*)d_in[13]; const float* be2 = (const float*)d_in[14];
    const float* We3 = (const float*)d_in[15]; const float* be3 = (const float*)d_in[16];
    const float* Wt0 = (const float*)d_in[17];
    const float* Wt1 = (const float*)d_in[18];
    const float* Wt2 = (const float*)d_in[19];
    const float* Ws1 = (const float*)d_in[20]; const float* bs1 = (const float*)d_in[21];
    const float* Ws2 = (const float*)d_in[22]; const float* bs2 = (const float*)d_in[23];
    const float* lng = (const float*)d_in[24]; const float* lnb = (const float*)d_in[25];

    int N = in_sizes[0];
    int E = in_sizes[2];
    int ntypes = in_sizes[6] / 32;
    float* outX  = (float*)d_out;
    float* outEF = outX + (size_t)N * 32 * 9;

    cudaFuncSetAttribute(edge_kernel, cudaFuncAttributeMaxDynamicSharedMemorySize, EDGE_SMEM);
    cudaFuncSetAttribute(node_kernel, cudaFuncAttributeMaxDynamicSharedMemorySize, NODE_SMEM);

    zh_kernel<<<ntypes, 64>>>(emb, We2, ntypes);
    ptab_kernel<<<(ntypes * ntypes + 7) / 8, 256>>>(be2, ntypes);
    prep_kernel<<<1024, 256>>>(src, dst, node_type, bond_dist, bond_vec, N, E, ntypes);
    edge_kernel<<<592, 256, EDGE_SMEM>>>(edge_attr, dst, Wd1, bd1, Wd2, bd2, Wd3, bd3,
                                         We3, be3, outEF, E);
    node_kernel<<<444, 256, NODE_SMEM>>>(Ws1, bs1, Ws2, bs2, Wt0, Wt1, Wt2, lng, lnb, outX, N);
}

// round 14
// speedup vs baseline: 1.1503x; 1.0166x over previous
#include <cuda_runtime.h>

#define FULLMASK 0xffffffffu

// ---------------- persistent device scratch ----------------
// Accumulator component-major contiguous: [n][10 comps][32 ch] = 320 floats/node
__device__ __align__(16) float g_acc[20000 * 320];         // 25.6 MB
__device__ float g_ptab[95 * 95 * 32];                     // 1.15 MB, L2-hot
__device__ int   g_pidx[200000];
__device__ __align__(16) float4 g_geo[200000];             // (C, vx, vy, vz)

__device__ __forceinline__ void red_add_v2(float* a, float x, float y) {
    asm volatile("red.global.add.v2.f32 [%0], {%1,%2};"
                 :: "l"(a), "f"(x), "f"(y) : "memory");
}
__device__ __forceinline__ float2 ffma2(float2 a, float2 b, float2 c) {
    float2 d;
    asm("fma.rn.f32x2 %0, %1, %2, %3;"
        : "=l"(*(unsigned long long*)&d)
        : "l"(*(unsigned long long*)&a),
          "l"(*(unsigned long long*)&b),
          "l"(*(unsigned long long*)&c));
    return d;
}

// ---------------- fused precompute: zero + geo/pidx + ptab ----------------
__global__ __launch_bounds__(256) void pre_kernel(
    const int* __restrict__ src, const int* __restrict__ dst,
    const int* __restrict__ ntype,
    const float* __restrict__ bdist, const float* __restrict__ bvec,
    const float* __restrict__ emb, const float* __restrict__ We2,
    const float* __restrict__ be2,
    int N, int E, int ntypes)
{
    int stride = gridDim.x * blockDim.x;
    int g = blockIdx.x * blockDim.x + threadIdx.x;
    // zero accumulator (contiguous, no predicate)
    int n4 = N * 80;   // N*320 floats / 4
    float4* acc4 = reinterpret_cast<float4*>(g_acc);
    float4 z = make_float4(0.f, 0.f, 0.f, 0.f);
    for (int i = g; i < n4; i += stride) acc4[i] = z;
    // per-edge geometry + pair index
    for (int e = g; e < E; e += stride) {
        g_pidx[e] = ntype[src[e]] * ntypes + ntype[dst[e]];
        float dd = bdist[e];
        float c = 0.5f * (__cosf(0.62831853071795864769f * dd) + 1.f);
        c = (dd <= 5.0f) ? c : 0.f;
        float bx = bvec[(size_t)e * 3], by = bvec[(size_t)e * 3 + 1], bz = bvec[(size_t)e * 3 + 2];
        float inv = rsqrtf(bx * bx + by * by + bz * bz);
        g_geo[e] = make_float4(c, bx * inv, by * inv, bz * inv);
    }
    // pair table directly from emb & We2 (warp per pair)
    int nw = stride >> 5;
    int wid = g >> 5;
    int u = threadIdx.x & 31;
    int npairs = ntypes * ntypes;
    for (int p = wid; p < npairs; p += nw) {
        int ts = p / ntypes, td = p - ts * ntypes;
        const float* es = emb + ts * 32;
        const float* ed = emb + td * 32;
        float s = be2[u];
#pragma unroll 8
        for (int k = 0; k < 32; k++) {
            s = fmaf(__ldg(es + k), We2[k * 32 + u], s);
            s = fmaf(__ldg(ed + k), We2[(k + 32) * 32 + u], s);
        }
        g_ptab[(size_t)p * 32 + u] = s;
    }
}

// ---------------- edge phase (R9/R13 proven: 16 edges/warp, unroll 2) ----------------
struct alignas(16) EdgeSmem16 {
    float4 WaP[64 * 16];
    float4 WbP[64 * 16];
    float4 adup[8][64][9];
    float4 geos[8][16];
    int    dns[8][16];
    int    pids[8][16];
};
static constexpr int EDGE_SMEM = (int)sizeof(EdgeSmem16);

__global__ __launch_bounds__(256, 2) void edge_kernel(
    const float* __restrict__ ea, const int* __restrict__ dst,
    const float* __restrict__ Wd1, const float* __restrict__ bd1,
    const float* __restrict__ Wd2, const float* __restrict__ bd2,
    const float* __restrict__ Wd3, const float* __restrict__ bd3,
    const float* __restrict__ We3, const float* __restrict__ be3,
    float* __restrict__ outEF, int E)
{
    extern __shared__ __align__(16) char smraw[];
    EdgeSmem16& sm = *reinterpret_cast<EdgeSmem16*>(smraw);
    int tid = threadIdx.x;
    for (int i = tid; i < 64 * 16; i += 256) {
        int k = i >> 4, c2 = (i & 15) * 2;
        sm.WaP[i] = make_float4(Wd1[k * 32 + c2], Wd1[k * 32 + c2 + 1],
                                Wd2[k * 32 + c2], Wd2[k * 32 + c2 + 1]);
        sm.WbP[i] = make_float4(Wd3[k * 32 + c2], Wd3[k * 32 + c2 + 1],
                                We3[k * 32 + c2], We3[k * 32 + c2 + 1]);
    }
    __syncthreads();
    const int u = tid & 31, w = tid >> 5;
    const int c = u & 15, h = u >> 4;
    const float2 bias1 = make_float2(bd1[2 * c], bd1[2 * c + 1]);
    const float2 bias2 = make_float2(bd2[2 * c], bd2[2 * c + 1]);
    const float2 bias3 = make_float2(bd3[2 * c], bd3[2 * c + 1]);
    const float2 biase = make_float2(be3[2 * c], be3[2 * c + 1]);
    int gw = blockIdx.x * 8 + w;
    int nw = gridDim.x * 8;
    int ngroups = (E + 15) >> 4;
    for (int g = gw; g < ngroups; g += nw) {
        int e0 = g * 16;
        __syncwarp();
        {
            float a0[16], a1[16];
#pragma unroll
            for (int j = 0; j < 16; j++) {
                int e = min(e0 + j, E - 1);
                a0[j] = ea[(size_t)e * 64 + u];
                a1[j] = ea[(size_t)e * 64 + 32 + u];
            }
#pragma unroll
            for (int q = 0; q < 8; q++) {
                sm.adup[w][u][q]      = make_float4(a0[2 * q], a0[2 * q], a0[2 * q + 1], a0[2 * q + 1]);
                sm.adup[w][u + 32][q] = make_float4(a1[2 * q], a1[2 * q], a1[2 * q + 1], a1[2 * q + 1]);
            }
            if (u < 16) {
                int e = min(e0 + u, E - 1);
                sm.geos[w][u] = g_geo[e];
                sm.dns[w][u] = dst[e];
                sm.pids[w][u] = g_pidx[e];
            }
        }
        __syncwarp();
        float2 w1[8], w2[8], w3[8], ef[8];
#pragma unroll
        for (int j = 0; j < 8; j++) { w1[j] = bias1; w2[j] = bias2; w3[j] = bias3; ef[j] = biase; }
#pragma unroll 2
        for (int k = 0; k < 64; k++) {
            float4 wa = sm.WaP[k * 16 + c];
            float4 wb = sm.WbP[k * 16 + c];
            float4 A0 = sm.adup[w][k][4 * h + 0];
            float4 A1 = sm.adup[w][k][4 * h + 1];
            float4 A2 = sm.adup[w][k][4 * h + 2];
            float4 A3 = sm.adup[w][k][4 * h + 3];
            float2 d1 = make_float2(wa.x, wa.y);
            float2 d2 = make_float2(wa.z, wa.w);
            float2 d3 = make_float2(wb.x, wb.y);
            float2 de = make_float2(wb.z, wb.w);
            float2 ap0 = make_float2(A0.x, A0.y), ap1 = make_float2(A0.z, A0.w);
            float2 ap2 = make_float2(A1.x, A1.y), ap3 = make_float2(A1.z, A1.w);
            float2 ap4 = make_float2(A2.x, A2.y), ap5 = make_float2(A2.z, A2.w);
            float2 ap6 = make_float2(A3.x, A3.y), ap7 = make_float2(A3.z, A3.w);
            w1[0] = ffma2(ap0, d1, w1[0]); w2[0] = ffma2(ap0, d2, w2[0]);
            w3[0] = ffma2(ap0, d3, w3[0]); ef[0] = ffma2(ap0, de, ef[0]);
            w1[1] = ffma2(ap1, d1, w1[1]); w2[1] = ffma2(ap1, d2, w2[1]);
            w3[1] = ffma2(ap1, d3, w3[1]); ef[1] = ffma2(ap1, de, ef[1]);
            w1[2] = ffma2(ap2, d1, w1[2]); w2[2] = ffma2(ap2, d2, w2[2]);
            w3[2] = ffma2(ap2, d3, w3[2]); ef[2] = ffma2(ap2, de, ef[2]);
            w1[3] = ffma2(ap3, d1, w1[3]); w2[3] = ffma2(ap3, d2, w2[3]);
            w3[3] = ffma2(ap3, d3, w3[3]); ef[3] = ffma2(ap3, de, ef[3]);
            w1[4] = ffma2(ap4, d1, w1[4]); w2[4] = ffma2(ap4, d2, w2[4]);
            w3[4] = ffma2(ap4, d3, w3[4]); ef[4] = ffma2(ap4, de, ef[4]);
            w1[5] = ffma2(ap5, d1, w1[5]); w2[5] = ffma2(ap5, d2, w2[5]);
            w3[5] = ffma2(ap5, d3, w3[5]); ef[5] = ffma2(ap5, de, ef[5]);
            w1[6] = ffma2(ap6, d1, w1[6]); w2[6] = ffma2(ap6, d2, w2[6]);
            w3[6] = ffma2(ap6, d3, w3[6]); ef[6] = ffma2(ap6, de, ef[6]);
            w1[7] = ffma2(ap7, d1, w1[7]); w2[7] = ffma2(ap7, d2, w2[7]);
            w3[7] = ffma2(ap7, d3, w3[7]); ef[7] = ffma2(ap7, de, ef[7]);
        }
#pragma unroll
        for (int j = 0; j < 8; j++) {
            int el = 8 * h + j;
            int e = e0 + el;
            if (e < E) {
                *reinterpret_cast<float2*>(&outEF[(size_t)e * 32 + 2 * c]) = ef[j];
                float4 gg = sm.geos[w][el];
                int dnj = sm.dns[w][el];
                float2 zj = *reinterpret_cast<const float2*>(&g_ptab[(size_t)sm.pids[w][el] * 32 + 2 * c]);
                float C = gg.x, vx = gg.y, vy = gg.z, vz = gg.w;
                float zcx = zj.x * C, zcy = zj.y * C;
                float fIx = zcx * w1[j].x, fIy = zcy * w1[j].y;
                float px = zcx * w2[j].x, py = zcy * w2[j].y;
                float qx = zcx * w3[j].x, qy = zcy * w3[j].y;
                float* base = g_acc + (size_t)dnj * 320 + 2 * c;
                red_add_v2(base,       fIx,          fIy);
                red_add_v2(base + 32,  px * vx,      py * vx);
                red_add_v2(base + 64,  px * vy,      py * vy);
                red_add_v2(base + 96,  px * vz,      py * vz);
                red_add_v2(base + 128, qx * vx * vx, qy * vx * vx);
                red_add_v2(base + 160, qx * vy * vy, qy * vy * vy);
                red_add_v2(base + 192, qx * vz * vz, qy * vz * vz);
                red_add_v2(base + 224, qx * vx * vy, qy * vx * vy);
                red_add_v2(base + 256, qx * vx * vz, qy * vx * vz);
                red_add_v2(base + 288, qx * vy * vz, qy * vy * vz);
            }
        }
    }
}

// ---------------- node epilogue v3: packed MLP + coalesced output ----------------
struct alignas(16) NodeSmem {
    float2 W1p[32 * 32];        //  8 KB : (Ws1[k][u], Ws1[k][u+32])
    float2 W2p[64 * 32];        // 16 KB : (Ws2[k][3u], Ws2[k][3u+1])
    float  W2c[64 * 32];        //  8 KB : Ws2[k][3u+2]
    float  Wt0s[32 * 32];       //  4 KB
    float  Wt1s[32 * 32];       //  4 KB
    float  Wt2s[32 * 32];       //  4 KB
    float2 b1p[32];
    float2 b2p[32];
    float  b2c[32];
    float  lngs[32], lnbs[32];
    float  wbuf[8][64];         //  2 KB
    float4 comps[8][32][3];     // 12 KB
    float  obuf[8][288];        //  9 KB : per-warp staged output
};
static constexpr int NODE_SMEM = (int)sizeof(NodeSmem);

__global__ __launch_bounds__(256, 3) void node_kernel(
    const float* __restrict__ Ws1, const float* __restrict__ bs1,
    const float* __restrict__ Ws2, const float* __restrict__ bs2,
    const float* __restrict__ Wt0, const float* __restrict__ Wt1, const float* __restrict__ Wt2,
    const float* __restrict__ lng, const float* __restrict__ lnb,
    float* __restrict__ outX, int N)
{
    extern __shared__ __align__(16) char smraw[];
    NodeSmem& sm = *reinterpret_cast<NodeSmem*>(smraw);
    int tid = threadIdx.x;
    for (int i = tid; i < 32 * 32; i += 256) {
        int k = i >> 5, uu = i & 31;
        sm.W1p[i] = make_float2(Ws1[k * 64 + uu], Ws1[k * 64 + uu + 32]);
        sm.Wt0s[i] = Wt0[i]; sm.Wt1s[i] = Wt1[i]; sm.Wt2s[i] = Wt2[i];
    }
    for (int i = tid; i < 64 * 32; i += 256) {
        int k = i >> 5, uu = i & 31;
        sm.W2p[i] = make_float2(Ws2[k * 96 + 3 * uu], Ws2[k * 96 + 3 * uu + 1]);
        sm.W2c[i] = Ws2[k * 96 + 3 * uu + 2];
    }
    if (tid < 32) {
        sm.b1p[tid] = make_float2(bs1[tid], bs1[tid + 32]);
        sm.b2p[tid] = make_float2(bs2[3 * tid], bs2[3 * tid + 1]);
        sm.b2c[tid] = bs2[3 * tid + 2];
        sm.lngs[tid] = lng[tid]; sm.lnbs[tid] = lnb[tid];
    }
    __syncthreads();
    const int u = tid & 31, w = tid >> 5;
    float* wb = sm.wbuf[w];
    float* ob = sm.obuf[w];
    int gw = blockIdx.x * 8 + w, nw = gridDim.x * 8;
    for (int n = gw; n < N; n += nw) {
        const float* base = g_acc + (size_t)n * 320 + u;
        float sI  = base[0];
        float wx  = base[32],  wy  = base[64],  wz  = base[96];
        float Mxx = base[128], Myy = base[160], Mzz = base[192];
        float Mxy = base[224], Mxz = base[256], Myz = base[288];
        sm.comps[w][u][0] = make_float4(sI, wx, wy, wz);
        sm.comps[w][u][1] = make_float4(Mxx, Myy, Mzz, Mxy);
        sm.comps[w][u][2] = make_float4(Mxz, Myz, 0.f, 0.f);
        float trM = Mxx + Myy + Mzz;
        float dg = sI - trM * (1.f / 3.f);
        float t00 = dg + Mxx, t11 = dg + Myy, t22 = dg + Mzz;
        float nr = t00 * t00 + t11 * t11 + t22 * t22
                 + 2.f * (Mxy * Mxy + wz * wz + Mxz * Mxz + wy * wy + Myz * Myz + wx * wx);
        float s = nr;
#pragma unroll
        for (int o = 16; o; o >>= 1) s += __shfl_xor_sync(FULLMASK, s, o);
        float mu = s * (1.f / 32.f);
        float dv = nr - mu;
        float v2 = dv * dv;
#pragma unroll
        for (int o = 16; o; o >>= 1) v2 += __shfl_xor_sync(FULLMASK, v2, o);
        float y = dv * rsqrtf(v2 * (1.f / 32.f) + 1e-5f) * sm.lngs[u] + sm.lnbs[u];
        wb[u] = y;
        __syncwarp();
        // MLP1: [32]->[64], packed pairs (u, u+32)
        float2 h1 = sm.b1p[u];
#pragma unroll 8
        for (int k = 0; k < 32; k++) {
            float t = wb[k];
            h1 = ffma2(make_float2(t, t), sm.W1p[k * 32 + u], h1);
        }
        float h1a = h1.x / (1.f + __expf(-h1.x));
        float h1b = h1.y / (1.f + __expf(-h1.y));
        __syncwarp();
        wb[u] = h1a; wb[u + 32] = h1b;
        __syncwarp();
        // MLP2: [64]->[96], packed (3u,3u+1) + scalar 3u+2
        float2 s01 = sm.b2p[u];
        float s2 = sm.b2c[u];
#pragma unroll 8
        for (int k = 0; k < 64; k++) {
            float t = wb[k];
            s01 = ffma2(make_float2(t, t), sm.W2p[k * 32 + u], s01);
            s2 = fmaf(t, sm.W2c[k * 32 + u], s2);
        }
        float s0 = s01.x / (1.f + __expf(-s01.x));
        float s1 = s01.y / (1.f + __expf(-s01.y));
        s2 = s2 / (1.f + __expf(-s2));
        // mixing: 5 packed accumulators, broadcast LDS operands
        float2 A0 = make_float2(0.f, 0.f);   // (pI,  px)
        float2 A1 = make_float2(0.f, 0.f);   // (py,  pz)
        float2 A2 = make_float2(0.f, 0.f);   // (pxx, pyy)
        float2 A3 = make_float2(0.f, 0.f);   // (pzz, pxy)
        float2 A4 = make_float2(0.f, 0.f);   // (pxz, pyz)
#pragma unroll 4
        for (int k = 0; k < 32; k++) {
            float w0v = sm.Wt0s[k * 32 + u];
            float w1v = sm.Wt1s[k * 32 + u];
            float w2v = sm.Wt2s[k * 32 + u];
            float4 c01 = sm.comps[w][k][0];
            float4 c2  = sm.comps[w][k][1];
            float4 c3  = sm.comps[w][k][2];
            A0 = ffma2(make_float2(c01.x, c01.y), make_float2(w0v, w1v), A0);
            A1 = ffma2(make_float2(c01.z, c01.w), make_float2(w1v, w1v), A1);
            A2 = ffma2(make_float2(c2.x,  c2.y ), make_float2(w2v, w2v), A2);
            A3 = ffma2(make_float2(c2.z,  c2.w ), make_float2(w2v, w2v), A3);
            A4 = ffma2(make_float2(c3.x,  c3.y ), make_float2(w2v, w2v), A4);
        }
        float pI = A0.x, px = A0.y, py = A1.x, pz = A1.y;
        float pxx = A2.x, pyy = A2.y, pzz = A3.x, pxy = A3.y, pxz = A4.x, pyz = A4.y;
        float t3 = (pxx + pyy + pzz) * (1.f / 3.f);
        // stage 9 outputs in smem (stride-9 STS: conflict-free, gcd(9,32)=1)
        float* po = ob + u * 9;
        po[0] =  s0 * pI + s2 * (pxx - t3);
        po[1] = -s1 * pz + s2 * pxy;
        po[2] =  s1 * py + s2 * pxz;
        po[3] =  s1 * pz + s2 * pxy;
        po[4] =  s0 * pI + s2 * (pyy - t3);
        po[5] = -s1 * px + s2 * pyz;
        po[6] = -s1 * py + s2 * pxz;
        po[7] =  s1 * px + s2 * pyz;
        po[8] =  s0 * pI + s2 * (pzz - t3);
        __syncwarp();
        // coalesced copy: 72 float4 per node
        float4* out4 = reinterpret_cast<float4*>(outX + (size_t)n * 288);
        const float4* ob4 = reinterpret_cast<const float4*>(ob);
#pragma unroll
        for (int i4 = 0; i4 < 2; i4++) out4[u + 32 * i4] = ob4[u + 32 * i4];
        if (u < 8) out4[u + 64] = ob4[u + 64];
        __syncwarp();
    }
}

extern "C" void kernel_launch(void* const* d_in, const int* in_sizes, int n_in,
                              void* d_out, int out_size) {
    (void)n_in; (void)out_size;
    const int*   node_type = (const int*)d_in[0];
    const float* edge_attr = (const float*)d_in[1];
    const float* bond_dist = (const float*)d_in[2];
    const float* bond_vec  = (const float*)d_in[3];
    const int*   src = (const int*)d_in[4];
    const int*   dst = (const int*)d_in[5];
    const float* emb = (const float*)d_in[6];
    const float* Wd1 = (const float*)d_in[7];  const float* bd1 = (const float*)d_in[8];
    const float* Wd2 = (const float*)d_in[9];  const float* bd2 = (const float*)d_in[10];
    const float* Wd3 = (const float*)d_in[11]; const float* bd3 = (const float*)d_in[12];
    const float* We2 = (const float*)d_in[13]; const float* be2 = (const float*)d_in[14];
    const float* We3 = (const float*)d_in[15]; const float* be3 = (const float*)d_in[16];
    const float* Wt0 = (const float*)d_in[17];
    const float* Wt1 = (const float*)d_in[18];
    const float* Wt2 = (const float*)d_in[19];
    const float* Ws1 = (const float*)d_in[20]; const float* bs1 = (const float*)d_in[21];
    const float* Ws2 = (const float*)d_in[22]; const float* bs2 = (const float*)d_in[23];
    const float* lng = (const float*)d_in[24]; const float* lnb = (const float*)d_in[25];

    int N = in_sizes[0];
    int E = in_sizes[2];
    int ntypes = in_sizes[6] / 32;
    float* outX  = (float*)d_out;
    float* outEF = outX + (size_t)N * 32 * 9;

    cudaFuncSetAttribute(edge_kernel, cudaFuncAttributeMaxDynamicSharedMemorySize, EDGE_SMEM);
    cudaFuncSetAttribute(node_kernel, cudaFuncAttributeMaxDynamicSharedMemorySize, NODE_SMEM);

    pre_kernel<<<1024, 256>>>(src, dst, node_type, bond_dist, bond_vec,
                              emb, We2, be2, N, E, ntypes);
    edge_kernel<<<592, 256, EDGE_SMEM>>>(edge_attr, dst, Wd1, bd1, Wd2, bd2, Wd3, bd3,
                                         We3, be3, outEF, E);
    node_kernel<<<444, 256, NODE_SMEM>>>(Ws1, bs1, Ws2, bs2, Wt0, Wt1, Wt2, lng, lnb, outX, N);
}